// round 5
// baseline (speedup 1.0000x reference)
#include <cuda_runtime.h>
#include <cuda_bf16.h>
#include <stdint.h>
#include <math.h>

#define NB 32
#define CC 256
#define HW 3136
#define PI_HALF 1.57079632679489662f

__device__ __nv_bfloat16 g_xh[NB][CC][HW];
__device__ __nv_bfloat16 g_xl[NB][CC][HW];
__device__ float g_gramp[2][NB][CC][CC];
__device__ float g_rowsum[NB][CC];
__device__ float g_u[NB][CC];
__device__ float g_v[NB][CC];
__device__ __nv_bfloat16 g_wph[CC][CC];
__device__ __nv_bfloat16 g_wpl[CC][CC];
__device__ __nv_bfloat16 g_t7h[NB][CC][CC];   // t7^T [d][c], bf16 hi
__device__ __nv_bfloat16 g_t7l[NB][CC][CC];   // t7^T [d][c], bf16 lo

__device__ __forceinline__ uint32_t smem_u32(const void* p) {
    uint32_t a;
    asm("{ .reg .u64 t; cvta.to.shared.u64 t, %1; cvt.u32.u64 %0, t; }"
        : "=r"(a) : "l"(p));
    return a;
}
__device__ __forceinline__ void cpa(uint32_t s, const void* g) {
    asm volatile("cp.async.cg.shared.global [%0], [%1], 16;" :: "r"(s), "l"(g));
}
#define CPA_COMMIT() asm volatile("cp.async.commit_group;" ::: "memory")
#define CPA_WAIT1()  asm volatile("cp.async.wait_group 1;" ::: "memory")
#define CPA_WAIT0()  asm volatile("cp.async.wait_group 0;" ::: "memory")

__device__ __forceinline__ void ldsm4(uint32_t r[4], uint32_t a) {
    asm volatile("ldmatrix.sync.aligned.m8n8.x4.shared.b16 {%0,%1,%2,%3}, [%4];"
                 : "=r"(r[0]), "=r"(r[1]), "=r"(r[2]), "=r"(r[3]) : "r"(a));
}
__device__ __forceinline__ void ldsm4t(uint32_t r[4], uint32_t a) {
    asm volatile("ldmatrix.sync.aligned.m8n8.x4.trans.shared.b16 {%0,%1,%2,%3}, [%4];"
                 : "=r"(r[0]), "=r"(r[1]), "=r"(r[2]), "=r"(r[3]) : "r"(a));
}
__device__ __forceinline__ void mma_bf16(float c[4], const uint32_t a[4],
                                         const uint32_t b[2]) {
    asm volatile(
        "mma.sync.aligned.m16n8k16.row.col.f32.bf16.bf16.f32 "
        "{%0,%1,%2,%3}, {%4,%5,%6,%7}, {%8,%9}, {%0,%1,%2,%3};"
        : "+f"(c[0]), "+f"(c[1]), "+f"(c[2]), "+f"(c[3])
        : "r"(a[0]), "r"(a[1]), "r"(a[2]), "r"(a[3]), "r"(b[0]), "r"(b[1]));
}
__device__ __forceinline__ uint32_t pk2(__nv_bfloat16 a, __nv_bfloat16 b) {
    unsigned short ua = *(unsigned short*)&a, ub = *(unsigned short*)&b;
    return (uint32_t)ua | ((uint32_t)ub << 16);
}
__device__ __forceinline__ float bflo(uint32_t v) {
    unsigned short u = (unsigned short)(v & 0xffffu);
    return __bfloat162float(*(__nv_bfloat16*)&u);
}
__device__ __forceinline__ float bfhi(uint32_t v) {
    unsigned short u = (unsigned short)(v >> 16);
    return __bfloat162float(*(__nv_bfloat16*)&u);
}

// ---- prep: x -> bf16 hi/lo + rowsums ----------------------------------------
__global__ void k_prep(const float* __restrict__ x) {
    const int n = blockIdx.y, c = blockIdx.x, t = threadIdx.x;
    const float4* row = (const float4*)(x + ((size_t)n * CC + c) * HW);
    uint2* oh = (uint2*)&g_xh[n][c][0];
    uint2* ol = (uint2*)&g_xl[n][c][0];
    float s = 0.f;
    for (int u = t; u < HW / 4; u += 256) {
        float4 v = row[u];
        s += v.x + v.y + v.z + v.w;
        __nv_bfloat16 h0 = __float2bfloat16(v.x), h1 = __float2bfloat16(v.y);
        __nv_bfloat16 h2 = __float2bfloat16(v.z), h3 = __float2bfloat16(v.w);
        uint2 ph, pl;
        ph.x = pk2(h0, h1); ph.y = pk2(h2, h3);
        pl.x = pk2(__float2bfloat16(v.x - __bfloat162float(h0)),
                   __float2bfloat16(v.y - __bfloat162float(h1)));
        pl.y = pk2(__float2bfloat16(v.z - __bfloat162float(h2)),
                   __float2bfloat16(v.w - __bfloat162float(h3)));
        oh[u] = ph; ol[u] = pl;
    }
#pragma unroll
    for (int o = 16; o; o >>= 1) s += __shfl_down_sync(0xffffffffu, s, o);
    __shared__ float red[8];
    if ((t & 31) == 0) red[t >> 5] = s;
    __syncthreads();
    if (t == 0) {
        float tt = 0.f;
#pragma unroll
        for (int q = 0; q < 8; q++) tt += red[q];
        g_rowsum[n][c] = tt;
    }
}

__global__ void k_wprep(const float* __restrict__ w) {
    const int o = blockIdx.x, i = threadIdx.x;
    const float v = w[o * 256 + i];
    __nv_bfloat16 h = __float2bfloat16(v);
    g_wph[o][i] = h;
    g_wpl[o][i] = __float2bfloat16(v - __bfloat162float(h));
}

__global__ void k_uv(const float* __restrict__ Wg1, const float* __restrict__ Wg2) {
    const int n = blockIdx.x, t = threadIdx.x;
    __shared__ float ss[256];
    ss[t] = g_rowsum[n][t];
    __syncthreads();
    const int g = t >> 5, r = t & 31;
    float u = 0.f, v = 0.f;
#pragma unroll
    for (int i = 0; i < 32; i++) {
        u += Wg1[(g * 32 + r) * 32 + i] * ss[g * 32 + i];
        v += Wg2[(g * 32 + r) * 32 + i] * ss[g * 32 + i];
    }
    g_u[n][t] = u;
    g_v[n][t] = v;
}

// ---- Gram = x x^T, symmetric-tile + K-split, cp.async double buffered -------
#define GSTRIDE 80u
#define GCH 10240
#define GRAM_SMEM (8 * GCH)

// grid (3, NB, 2): q=0 diag(0,0), q=1 diag(128,128), q=2 offdiag(0,128); z = ks
__global__ __launch_bounds__(256, 2) void k_gram() {
    extern __shared__ char sm[];
    const int q = blockIdx.x, n = blockIdx.y, ks = blockIdx.z;
    const int c0 = (q == 1) ? 128 : 0;
    const int d0 = (q == 0) ? 0 : 128;
    const bool diag = (q < 2);
    const int tid = threadIdx.x, lane = tid & 31, wid = tid >> 5;
    const int m0w = (wid & 1) * 64, n0w = (wid >> 1) * 32;
    const uint32_t smb = smem_u32(sm);

    const char* gAh = (const char*)&g_xh[n][c0][0];
    const char* gAl = (const char*)&g_xl[n][c0][0];
    const char* gBh = (const char*)&g_xh[n][d0][0];
    const char* gBl = (const char*)&g_xl[n][d0][0];

    const int lr = tid >> 1, ls = (tid & 1) * 32;
    const int a_r = lane & 15, a_kb = (lane >> 4) * 16;
    const int b_r = (lane & 7) + 8 * (lane >> 4);
    const int b_kb = ((lane >> 3) & 1) * 16;

    float acc[4][4][4];
#pragma unroll
    for (int i = 0; i < 4; i++)
#pragma unroll
        for (int j = 0; j < 4; j++)
#pragma unroll
            for (int p = 0; p < 4; p++) acc[i][j][p] = 0.f;

    const int ck0 = ks * 49;
    const uint32_t so = (uint32_t)lr * GSTRIDE + ls;

    // chunk layout: Ah at buf*2*GCH, Al at +GCH; Bh at 4*GCH + buf*2*GCH, Bl +GCH
    auto issueG = [&](int ci, int buf) {
        const size_t go = (size_t)lr * (HW * 2) + (size_t)(ck0 + ci) * 64 + ls;
        const uint32_t aH = smb + (buf * 2 + 0) * GCH + so;
        const uint32_t aL = smb + (buf * 2 + 1) * GCH + so;
        cpa(aH, gAh + go); cpa(aH + 16, gAh + go + 16);
        cpa(aL, gAl + go); cpa(aL + 16, gAl + go + 16);
        if (!diag) {
            const uint32_t bH = smb + 4 * GCH + (buf * 2 + 0) * GCH + so;
            const uint32_t bL = smb + 4 * GCH + (buf * 2 + 1) * GCH + so;
            cpa(bH, gBh + go); cpa(bH + 16, gBh + go + 16);
            cpa(bL, gBl + go); cpa(bL + 16, gBl + go + 16);
        }
    };

    issueG(0, 0);
    CPA_COMMIT();

    for (int ci = 0; ci < 49; ci++) {
        const int buf = ci & 1;
        if (ci < 48) { issueG(ci + 1, buf ^ 1); CPA_COMMIT(); CPA_WAIT1(); }
        else CPA_WAIT0();
        __syncthreads();

        const uint32_t aHb = smb + (buf * 2 + 0) * GCH;
        const uint32_t aLb = smb + (buf * 2 + 1) * GCH;
        const uint32_t bHb = diag ? aHb : smb + 4 * GCH + (buf * 2 + 0) * GCH;
        const uint32_t bLb = diag ? aLb : smb + 4 * GCH + (buf * 2 + 1) * GCH;
#pragma unroll
        for (int kk = 0; kk < 2; kk++) {
            const uint32_t kbo = kk * 32;
            uint32_t a[4][4], bh[4][2], bl[4][2];
#pragma unroll
            for (int mt = 0; mt < 4; mt++)
                ldsm4(a[mt], aHb + (uint32_t)(m0w + mt * 16 + a_r) * GSTRIDE + a_kb + kbo);
#pragma unroll
            for (int nt2 = 0; nt2 < 2; nt2++) {
                const uint32_t ro = (uint32_t)(n0w + nt2 * 16 + b_r) * GSTRIDE + b_kb + kbo;
                uint32_t t[4];
                ldsm4(t, bHb + ro);
                bh[nt2 * 2][0] = t[0]; bh[nt2 * 2][1] = t[1];
                bh[nt2 * 2 + 1][0] = t[2]; bh[nt2 * 2 + 1][1] = t[3];
                ldsm4(t, bLb + ro);
                bl[nt2 * 2][0] = t[0]; bl[nt2 * 2][1] = t[1];
                bl[nt2 * 2 + 1][0] = t[2]; bl[nt2 * 2 + 1][1] = t[3];
            }
#pragma unroll
            for (int mt = 0; mt < 4; mt++)
#pragma unroll
                for (int nt = 0; nt < 4; nt++) {
                    mma_bf16(acc[mt][nt], a[mt], bh[nt]);
                    mma_bf16(acc[mt][nt], a[mt], bl[nt]);
                }
#pragma unroll
            for (int mt = 0; mt < 4; mt++)
                ldsm4(a[mt], aLb + (uint32_t)(m0w + mt * 16 + a_r) * GSTRIDE + a_kb + kbo);
#pragma unroll
            for (int mt = 0; mt < 4; mt++)
#pragma unroll
                for (int nt = 0; nt < 4; nt++)
                    mma_bf16(acc[mt][nt], a[mt], bh[nt]);
        }
        __syncthreads();
    }

    float* gout = &g_gramp[ks][n][0][0];
#pragma unroll
    for (int mt = 0; mt < 4; mt++)
#pragma unroll
        for (int h = 0; h < 2; h++) {
            const int c = c0 + m0w + mt * 16 + (lane >> 2) + h * 8;
#pragma unroll
            for (int nt = 0; nt < 4; nt++) {
                const int d = d0 + n0w + nt * 8 + (lane & 3) * 2;
                const float v0 = acc[mt][nt][h * 2], v1 = acc[mt][nt][h * 2 + 1];
                *(float2*)(gout + (size_t)c * CC + d) = make_float2(v0, v1);
                if (!diag) {
                    gout[(size_t)d * CC + c] = v0;
                    gout[(size_t)(d + 1) * CC + c] = v1;
                }
            }
        }
}

// ---- t7^T (split bf16, pre-scaled by 1/(56*16)) ------------------------------
__global__ void k_t7(const float* __restrict__ Wg1, const float* __restrict__ bg1,
                     const float* __restrict__ Wg2, const float* __restrict__ bg2,
                     const float* __restrict__ p7w) {
    __shared__ float W1s[32][33], W2s[32][33], Gs[32][33], Ms[32][33];
    const int n = blockIdx.z, g = blockIdx.y, h = blockIdx.x;
    const int tx = threadIdx.x, ty = threadIdx.y;

    W1s[ty][tx] = Wg1[(g * 32 + ty) * 32 + tx];
    W2s[ty][tx] = Wg2[(h * 32 + ty) * 32 + tx];
    Gs[ty][tx]  = g_gramp[0][n][g * 32 + ty][h * 32 + tx]
                + g_gramp[1][n][g * 32 + ty][h * 32 + tx];
    __syncthreads();

    float m = 0.f;
#pragma unroll
    for (int i = 0; i < 32; i++) m += W1s[ty][i] * Gs[i][tx];
    Ms[ty][tx] = m;
    __syncthreads();

    float t5 = 0.f;
#pragma unroll
    for (int j = 0; j < 32; j++) t5 += Ms[ty][j] * W2s[tx][j];

    const int c = g * 32 + ty, d = h * 32 + tx;
    const float b1 = bg1[c], b2 = bg2[d];
    t5 += b1 * g_v[n][d] + g_u[n][c] * b2 + (float)HW * b1 * b2;
    const float val = p7w[c * 256 + d] * t5 * (1.0f / 896.0f);

    __syncthreads();
    W1s[ty][tx] = val;
    __syncthreads();
    const float tv = W1s[tx][ty];
    const int dd = h * 32 + ty, cc = g * 32 + tx;
    __nv_bfloat16 hh = __float2bfloat16(tv);
    g_t7h[n][dd][cc] = hh;
    g_t7l[n][dd][cc] = __float2bfloat16(tv - __bfloat162float(hh));
}

// ---- fused: flat 16-chunk pipeline, stage0 = Wp3@x, stage1 = t7^T@t6 --------
#define FLDB 144u
#define FBX 36864
#define FSTRIDE 80u
#define FACH 20480
#define FUSED_SMEM (2 * FBX + 4 * FACH)

__global__ __launch_bounds__(256, 1) void k_fused(const float* __restrict__ bp3,
                                                  float* __restrict__ out) {
    extern __shared__ char sm[];
    const int n = blockIdx.y, sx = blockIdx.x;
    const int tid = threadIdx.x, lane = tid & 31, wid = tid >> 5;
    const int m0w = (wid >> 1) * 64, n0w = (wid & 1) * 32;
    const uint32_t smb = smem_u32(sm);

    const int a_r = lane & 15, a_kb = (lane >> 4) * 16;
    const int bt_r = (lane & 7) + 8 * ((lane >> 3) & 1);
    const int bt_nb = (lane >> 4) * 16;

    float acc[4][4][4];
#pragma unroll
    for (int i = 0; i < 4; i++)
#pragma unroll
        for (int j = 0; j < 4; j++)
#pragma unroll
            for (int p = 0; p < 4; p++) acc[i][j][p] = 0.f;

    auto issueA = [&](int g1, int buf) {
        const char* Ah = (g1 < 8) ? (const char*)&g_wph[0][0] : (const char*)&g_t7h[n][0][0];
        const char* Al = (g1 < 8) ? (const char*)&g_wpl[0][0] : (const char*)&g_t7l[n][0][0];
        const int k0 = (g1 & 7) * 32;
        const uint32_t pH = smb + 2 * FBX + (buf * 2 + 0) * FACH;
        const uint32_t pL = smb + 2 * FBX + (buf * 2 + 1) * FACH;
#pragma unroll
        for (int i = 0; i < 4; i++) {
            const int idx = tid + i * 256;
            const int r = idx >> 2, s = (idx & 3) * 16;
            cpa(pH + (uint32_t)r * FSTRIDE + s, Ah + (size_t)r * 512 + k0 * 2 + s);
            cpa(pL + (uint32_t)r * FSTRIDE + s, Al + (size_t)r * 512 + k0 * 2 + s);
        }
    };

    {   // B = x stripe [256 k-rows][64 cols] hi/lo, async
        const char* srcH = (const char*)&g_xh[n][0][sx * 64];
        const char* srcL = (const char*)&g_xl[n][0][sx * 64];
#pragma unroll
        for (int i = 0; i < 8; i++) {
            const int idx = tid + i * 256;
            const int r = idx >> 3, s = (idx & 7) * 16;
            cpa(smb + (uint32_t)r * FLDB + s, srcH + (size_t)r * (HW * 2) + s);
            cpa(smb + FBX + (uint32_t)r * FLDB + s, srcL + (size_t)r * (HW * 2) + s);
        }
    }
    issueA(0, 0);
    CPA_COMMIT();

    for (int g = 0; g < 16; g++) {
        const int buf = g & 1;
        if (g < 15) { issueA(g + 1, buf ^ 1); CPA_COMMIT(); CPA_WAIT1(); }
        else CPA_WAIT0();
        __syncthreads();

        if (g == 8) {
            // epilogue stage0: t6 = max(t3 + bias, sin(pi/2 x)); rewrite B hi/lo
#pragma unroll
            for (int mt = 0; mt < 4; mt++)
#pragma unroll
                for (int h = 0; h < 2; h++) {
                    const int c = m0w + mt * 16 + (lane >> 2) + h * 8;
                    const float bias = __ldg(&bp3[c]);
#pragma unroll
                    for (int nt = 0; nt < 4; nt++) {
                        const int j = n0w + nt * 8 + (lane & 3) * 2;
                        uint32_t ph = *(uint32_t*)(sm + c * FLDB + j * 2);
                        uint32_t pl = *(uint32_t*)(sm + FBX + c * FLDB + j * 2);
                        const float x0 = bflo(ph) + bflo(pl);
                        const float x1 = bfhi(ph) + bfhi(pl);
                        const float t60 = fmaxf(acc[mt][nt][h * 2] + bias,
                                                sinf(PI_HALF * x0));
                        const float t61 = fmaxf(acc[mt][nt][h * 2 + 1] + bias,
                                                sinf(PI_HALF * x1));
                        __nv_bfloat16 h0 = __float2bfloat16(t60);
                        __nv_bfloat16 h1 = __float2bfloat16(t61);
                        *(uint32_t*)(sm + c * FLDB + j * 2) = pk2(h0, h1);
                        *(uint32_t*)(sm + FBX + c * FLDB + j * 2) =
                            pk2(__float2bfloat16(t60 - __bfloat162float(h0)),
                                __float2bfloat16(t61 - __bfloat162float(h1)));
                        acc[mt][nt][h * 2] = 0.f;
                        acc[mt][nt][h * 2 + 1] = 0.f;
                    }
                }
            __syncthreads();
        }

        const uint32_t aHb = smb + 2 * FBX + (buf * 2 + 0) * FACH;
        const uint32_t aLb = smb + 2 * FBX + (buf * 2 + 1) * FACH;
#pragma unroll
        for (int kk = 0; kk < 2; kk++) {
            uint32_t a[4][4], bh[4][2], bl[4][2];
#pragma unroll
            for (int mt = 0; mt < 4; mt++)
                ldsm4(a[mt], aHb + (uint32_t)(m0w + mt * 16 + a_r) * FSTRIDE + kk * 32 + a_kb);
            const int kg = (g & 7) * 32 + kk * 16;
#pragma unroll
            for (int nt2 = 0; nt2 < 2; nt2++) {
                const uint32_t ro = (uint32_t)(kg + bt_r) * FLDB + (n0w + nt2 * 16) * 2 + bt_nb;
                uint32_t t[4];
                ldsm4t(t, smb + ro);
                bh[nt2 * 2][0] = t[0]; bh[nt2 * 2][1] = t[1];
                bh[nt2 * 2 + 1][0] = t[2]; bh[nt2 * 2 + 1][1] = t[3];
                ldsm4t(t, smb + FBX + ro);
                bl[nt2 * 2][0] = t[0]; bl[nt2 * 2][1] = t[1];
                bl[nt2 * 2 + 1][0] = t[2]; bl[nt2 * 2 + 1][1] = t[3];
            }
#pragma unroll
            for (int mt = 0; mt < 4; mt++)
#pragma unroll
                for (int nt = 0; nt < 4; nt++) {
                    mma_bf16(acc[mt][nt], a[mt], bh[nt]);
                    mma_bf16(acc[mt][nt], a[mt], bl[nt]);
                }
#pragma unroll
            for (int mt = 0; mt < 4; mt++)
                ldsm4(a[mt], aLb + (uint32_t)(m0w + mt * 16 + a_r) * FSTRIDE + kk * 32 + a_kb);
#pragma unroll
            for (int mt = 0; mt < 4; mt++)
#pragma unroll
                for (int nt = 0; nt < 4; nt++)
                    mma_bf16(acc[mt][nt], a[mt], bh[nt]);
        }
        __syncthreads();
    }

    float* ob = out + (size_t)n * CC * HW + sx * 64;
#pragma unroll
    for (int mt = 0; mt < 4; mt++)
#pragma unroll
        for (int h = 0; h < 2; h++) {
            const int d = m0w + mt * 16 + (lane >> 2) + h * 8;
#pragma unroll
            for (int nt = 0; nt < 4; nt++) {
                const int j = n0w + nt * 8 + (lane & 3) * 2;
                *(float2*)(ob + (size_t)d * HW + j) =
                    make_float2(acc[mt][nt][h * 2], acc[mt][nt][h * 2 + 1]);
            }
        }
}

extern "C" void kernel_launch(void* const* d_in, const int* in_sizes, int n_in,
                              void* d_out, int out_size) {
    (void)in_sizes; (void)n_in; (void)out_size;
    const float* x   = (const float*)d_in[0];
    const float* Wp3 = (const float*)d_in[1];
    const float* bp3 = (const float*)d_in[2];
    const float* Wg1 = (const float*)d_in[3];
    const float* bg1 = (const float*)d_in[4];
    const float* Wg2 = (const float*)d_in[5];
    const float* bg2 = (const float*)d_in[6];
    const float* p7w = (const float*)d_in[7];
    float* out = (float*)d_out;

    cudaFuncSetAttribute(k_gram,  cudaFuncAttributeMaxDynamicSharedMemorySize, GRAM_SMEM);
    cudaFuncSetAttribute(k_fused, cudaFuncAttributeMaxDynamicSharedMemorySize, FUSED_SMEM);

    k_wprep<<<256, 256>>>(Wp3);
    k_prep<<<dim3(256, 32), 256>>>(x);
    k_uv<<<32, 256>>>(Wg1, Wg2);
    k_gram<<<dim3(3, 32, 2), 256, GRAM_SMEM>>>();
    k_t7<<<dim3(8, 8, 32), dim3(32, 32)>>>(Wg1, bg1, Wg2, bg2, p7w);
    k_fused<<<dim3(49, 32), 256, FUSED_SMEM>>>(bp3, out);
}

// round 6
// speedup vs baseline: 1.1612x; 1.1612x over previous
#include <cuda_runtime.h>
#include <cuda_bf16.h>
#include <stdint.h>
#include <math.h>

#define NB 32
#define CC 256
#define HW 3136
#define PI_HALF 1.57079632679489662f

__device__ __nv_bfloat16 g_xh[NB][CC][HW];
__device__ __nv_bfloat16 g_xl[NB][CC][HW];
__device__ float g_gramp[3][NB][CC][CC];
__device__ float g_rowsum[NB][CC];
__device__ float g_u[NB][CC];
__device__ float g_v[NB][CC];
__device__ __nv_bfloat16 g_wph[CC][CC];
__device__ __nv_bfloat16 g_wpl[CC][CC];
__device__ __nv_bfloat16 g_t7h[NB][CC][CC];   // t7^T [d][c], bf16 hi
__device__ __nv_bfloat16 g_t7l[NB][CC][CC];   // t7^T [d][c], bf16 lo

__device__ __forceinline__ uint32_t smem_u32(const void* p) {
    uint32_t a;
    asm("{ .reg .u64 t; cvta.to.shared.u64 t, %1; cvt.u32.u64 %0, t; }"
        : "=r"(a) : "l"(p));
    return a;
}
__device__ __forceinline__ void cpa(uint32_t s, const void* g) {
    asm volatile("cp.async.cg.shared.global [%0], [%1], 16;" :: "r"(s), "l"(g));
}
#define CPA_COMMIT() asm volatile("cp.async.commit_group;" ::: "memory")
#define CPA_WAIT1()  asm volatile("cp.async.wait_group 1;" ::: "memory")
#define CPA_WAIT0()  asm volatile("cp.async.wait_group 0;" ::: "memory")

__device__ __forceinline__ void ldsm4(uint32_t r[4], uint32_t a) {
    asm volatile("ldmatrix.sync.aligned.m8n8.x4.shared.b16 {%0,%1,%2,%3}, [%4];"
                 : "=r"(r[0]), "=r"(r[1]), "=r"(r[2]), "=r"(r[3]) : "r"(a));
}
__device__ __forceinline__ void ldsm4t(uint32_t r[4], uint32_t a) {
    asm volatile("ldmatrix.sync.aligned.m8n8.x4.trans.shared.b16 {%0,%1,%2,%3}, [%4];"
                 : "=r"(r[0]), "=r"(r[1]), "=r"(r[2]), "=r"(r[3]) : "r"(a));
}
__device__ __forceinline__ void mma_bf16(float c[4], const uint32_t a[4],
                                         const uint32_t b[2]) {
    asm volatile(
        "mma.sync.aligned.m16n8k16.row.col.f32.bf16.bf16.f32 "
        "{%0,%1,%2,%3}, {%4,%5,%6,%7}, {%8,%9}, {%0,%1,%2,%3};"
        : "+f"(c[0]), "+f"(c[1]), "+f"(c[2]), "+f"(c[3])
        : "r"(a[0]), "r"(a[1]), "r"(a[2]), "r"(a[3]), "r"(b[0]), "r"(b[1]));
}
__device__ __forceinline__ uint32_t pk2(__nv_bfloat16 a, __nv_bfloat16 b) {
    unsigned short ua = *(unsigned short*)&a, ub = *(unsigned short*)&b;
    return (uint32_t)ua | ((uint32_t)ub << 16);
}
__device__ __forceinline__ float bflo(uint32_t v) {
    unsigned short u = (unsigned short)(v & 0xffffu);
    return __bfloat162float(*(__nv_bfloat16*)&u);
}
__device__ __forceinline__ float bfhi(uint32_t v) {
    unsigned short u = (unsigned short)(v >> 16);
    return __bfloat162float(*(__nv_bfloat16*)&u);
}

// ---- prep: x -> bf16 hi/lo + rowsums ----------------------------------------
__global__ void k_prep(const float* __restrict__ x) {
    const int n = blockIdx.y, c = blockIdx.x, t = threadIdx.x;
    const float4* row = (const float4*)(x + ((size_t)n * CC + c) * HW);
    uint2* oh = (uint2*)&g_xh[n][c][0];
    uint2* ol = (uint2*)&g_xl[n][c][0];
    float s = 0.f;
    for (int u = t; u < HW / 4; u += 256) {
        float4 v = row[u];
        s += v.x + v.y + v.z + v.w;
        __nv_bfloat16 h0 = __float2bfloat16(v.x), h1 = __float2bfloat16(v.y);
        __nv_bfloat16 h2 = __float2bfloat16(v.z), h3 = __float2bfloat16(v.w);
        uint2 ph, pl;
        ph.x = pk2(h0, h1); ph.y = pk2(h2, h3);
        pl.x = pk2(__float2bfloat16(v.x - __bfloat162float(h0)),
                   __float2bfloat16(v.y - __bfloat162float(h1)));
        pl.y = pk2(__float2bfloat16(v.z - __bfloat162float(h2)),
                   __float2bfloat16(v.w - __bfloat162float(h3)));
        oh[u] = ph; ol[u] = pl;
    }
#pragma unroll
    for (int o = 16; o; o >>= 1) s += __shfl_down_sync(0xffffffffu, s, o);
    __shared__ float red[8];
    if ((t & 31) == 0) red[t >> 5] = s;
    __syncthreads();
    if (t == 0) {
        float tt = 0.f;
#pragma unroll
        for (int q = 0; q < 8; q++) tt += red[q];
        g_rowsum[n][c] = tt;
    }
}

__global__ void k_wprep(const float* __restrict__ w) {
    const int o = blockIdx.x, i = threadIdx.x;
    const float v = w[o * 256 + i];
    __nv_bfloat16 h = __float2bfloat16(v);
    g_wph[o][i] = h;
    g_wpl[o][i] = __float2bfloat16(v - __bfloat162float(h));
}

__global__ void k_uv(const float* __restrict__ Wg1, const float* __restrict__ Wg2) {
    const int n = blockIdx.x, t = threadIdx.x;
    __shared__ float ss[256];
    ss[t] = g_rowsum[n][t];
    __syncthreads();
    const int g = t >> 5, r = t & 31;
    float u = 0.f, v = 0.f;
#pragma unroll
    for (int i = 0; i < 32; i++) {
        u += Wg1[(g * 32 + r) * 32 + i] * ss[g * 32 + i];
        v += Wg2[(g * 32 + r) * 32 + i] * ss[g * 32 + i];
    }
    g_u[n][t] = u;
    g_v[n][t] = v;
}

// ---- Gram = x x^T, symmetric-tile, K-split x3, cp.async double buffered -----
#define GSTRIDE 80u
#define GCH 10240
#define GRAM_SMEM (8 * GCH)

// grid (3, NB, 3): q=0 diag(0,0), q=1 diag(128,128), q=2 offdiag(0,128); z=ks
__global__ __launch_bounds__(256, 2) void k_gram() {
    extern __shared__ char sm[];
    const int q = blockIdx.x, n = blockIdx.y, ks = blockIdx.z;
    const int c0 = (q == 1) ? 128 : 0;
    const int d0 = (q == 0) ? 0 : 128;
    const bool diag = (q < 2);
    const int tid = threadIdx.x, lane = tid & 31, wid = tid >> 5;
    const int m0w = (wid & 1) * 64, n0w = (wid >> 1) * 32;
    const uint32_t smb = smem_u32(sm);

    const char* gAh = (const char*)&g_xh[n][c0][0];
    const char* gAl = (const char*)&g_xl[n][c0][0];
    const char* gBh = (const char*)&g_xh[n][d0][0];
    const char* gBl = (const char*)&g_xl[n][d0][0];

    const int lr = tid >> 1, ls = (tid & 1) * 32;
    const int a_r = lane & 15, a_kb = (lane >> 4) * 16;
    const int b_r = (lane & 7) + 8 * (lane >> 4);
    const int b_kb = ((lane >> 3) & 1) * 16;

    float acc[4][4][4];
#pragma unroll
    for (int i = 0; i < 4; i++)
#pragma unroll
        for (int j = 0; j < 4; j++)
#pragma unroll
            for (int p = 0; p < 4; p++) acc[i][j][p] = 0.f;

    const int ck0 = ks * 33;
    const int nck = (ks < 2) ? 33 : 32;
    const uint32_t so = (uint32_t)lr * GSTRIDE + ls;

    auto issueG = [&](int ci, int buf) {
        const size_t go = (size_t)lr * (HW * 2) + (size_t)(ck0 + ci) * 64 + ls;
        const uint32_t aH = smb + (buf * 2 + 0) * GCH + so;
        const uint32_t aL = smb + (buf * 2 + 1) * GCH + so;
        cpa(aH, gAh + go); cpa(aH + 16, gAh + go + 16);
        cpa(aL, gAl + go); cpa(aL + 16, gAl + go + 16);
        if (!diag) {
            const uint32_t bH = smb + 4 * GCH + (buf * 2 + 0) * GCH + so;
            const uint32_t bL = smb + 4 * GCH + (buf * 2 + 1) * GCH + so;
            cpa(bH, gBh + go); cpa(bH + 16, gBh + go + 16);
            cpa(bL, gBl + go); cpa(bL + 16, gBl + go + 16);
        }
    };

    issueG(0, 0);
    CPA_COMMIT();

    for (int ci = 0; ci < nck; ci++) {
        const int buf = ci & 1;
        if (ci < nck - 1) { issueG(ci + 1, buf ^ 1); CPA_COMMIT(); CPA_WAIT1(); }
        else CPA_WAIT0();
        __syncthreads();

        const uint32_t aHb = smb + (buf * 2 + 0) * GCH;
        const uint32_t aLb = smb + (buf * 2 + 1) * GCH;
        const uint32_t bHb = diag ? aHb : smb + 4 * GCH + (buf * 2 + 0) * GCH;
        const uint32_t bLb = diag ? aLb : smb + 4 * GCH + (buf * 2 + 1) * GCH;
#pragma unroll
        for (int kk = 0; kk < 2; kk++) {
            const uint32_t kbo = kk * 32;
            uint32_t a[4][4], bh[4][2], bl[4][2];
#pragma unroll
            for (int mt = 0; mt < 4; mt++)
                ldsm4(a[mt], aHb + (uint32_t)(m0w + mt * 16 + a_r) * GSTRIDE + a_kb + kbo);
#pragma unroll
            for (int nt2 = 0; nt2 < 2; nt2++) {
                const uint32_t ro = (uint32_t)(n0w + nt2 * 16 + b_r) * GSTRIDE + b_kb + kbo;
                uint32_t t[4];
                ldsm4(t, bHb + ro);
                bh[nt2 * 2][0] = t[0]; bh[nt2 * 2][1] = t[1];
                bh[nt2 * 2 + 1][0] = t[2]; bh[nt2 * 2 + 1][1] = t[3];
                ldsm4(t, bLb + ro);
                bl[nt2 * 2][0] = t[0]; bl[nt2 * 2][1] = t[1];
                bl[nt2 * 2 + 1][0] = t[2]; bl[nt2 * 2 + 1][1] = t[3];
            }
#pragma unroll
            for (int mt = 0; mt < 4; mt++)
#pragma unroll
                for (int nt = 0; nt < 4; nt++) {
                    mma_bf16(acc[mt][nt], a[mt], bh[nt]);
                    mma_bf16(acc[mt][nt], a[mt], bl[nt]);
                }
#pragma unroll
            for (int mt = 0; mt < 4; mt++)
                ldsm4(a[mt], aLb + (uint32_t)(m0w + mt * 16 + a_r) * GSTRIDE + a_kb + kbo);
#pragma unroll
            for (int mt = 0; mt < 4; mt++)
#pragma unroll
                for (int nt = 0; nt < 4; nt++)
                    mma_bf16(acc[mt][nt], a[mt], bh[nt]);
        }
        __syncthreads();
    }

    float* gout = &g_gramp[ks][n][0][0];
#pragma unroll
    for (int mt = 0; mt < 4; mt++)
#pragma unroll
        for (int h = 0; h < 2; h++) {
            const int c = c0 + m0w + mt * 16 + (lane >> 2) + h * 8;
#pragma unroll
            for (int nt = 0; nt < 4; nt++) {
                const int d = d0 + n0w + nt * 8 + (lane & 3) * 2;
                const float v0 = acc[mt][nt][h * 2], v1 = acc[mt][nt][h * 2 + 1];
                *(float2*)(gout + (size_t)c * CC + d) = make_float2(v0, v1);
                if (!diag) {
                    gout[(size_t)d * CC + c] = v0;
                    gout[(size_t)(d + 1) * CC + c] = v1;
                }
            }
        }
}

// ---- t7^T (split bf16, pre-scaled by 1/(56*16)) ------------------------------
__global__ void k_t7(const float* __restrict__ Wg1, const float* __restrict__ bg1,
                     const float* __restrict__ Wg2, const float* __restrict__ bg2,
                     const float* __restrict__ p7w) {
    __shared__ float W1s[32][33], W2s[32][33], Gs[32][33], Ms[32][33];
    const int n = blockIdx.z, g = blockIdx.y, h = blockIdx.x;
    const int tx = threadIdx.x, ty = threadIdx.y;

    W1s[ty][tx] = Wg1[(g * 32 + ty) * 32 + tx];
    W2s[ty][tx] = Wg2[(h * 32 + ty) * 32 + tx];
    Gs[ty][tx]  = g_gramp[0][n][g * 32 + ty][h * 32 + tx]
                + g_gramp[1][n][g * 32 + ty][h * 32 + tx]
                + g_gramp[2][n][g * 32 + ty][h * 32 + tx];
    __syncthreads();

    float m = 0.f;
#pragma unroll
    for (int i = 0; i < 32; i++) m += W1s[ty][i] * Gs[i][tx];
    Ms[ty][tx] = m;
    __syncthreads();

    float t5 = 0.f;
#pragma unroll
    for (int j = 0; j < 32; j++) t5 += Ms[ty][j] * W2s[tx][j];

    const int c = g * 32 + ty, d = h * 32 + tx;
    const float b1 = bg1[c], b2 = bg2[d];
    t5 += b1 * g_v[n][d] + g_u[n][c] * b2 + (float)HW * b1 * b2;
    const float val = p7w[c * 256 + d] * t5 * (1.0f / 896.0f);

    __syncthreads();
    W1s[ty][tx] = val;
    __syncthreads();
    const float tv = W1s[tx][ty];
    const int dd = h * 32 + ty, cc = g * 32 + tx;
    __nv_bfloat16 hh = __float2bfloat16(tv);
    g_t7h[n][dd][cc] = hh;
    g_t7l[n][dd][cc] = __float2bfloat16(tv - __bfloat162float(hh));
}

// ---- fused: 32 chunks k=16, swizzled B, 2 CTAs/SM ----------------------------
// B stripe: [256 rows][128B] XOR-swizzled, hi at 0, lo at +FBX.
// A chunks: 256 rows x 16 kcols bf16, stride 48 (conflict-free), 4 buffers.
#define FBX 32768
#define FSTRIDE 48u
#define FACH 12288
#define FUSED_SMEM (2 * FBX + 4 * FACH)   // 114688

__device__ __forceinline__ uint32_t bswz(int row, int slot, int rem) {
    return (uint32_t)(row * 128 + ((slot ^ (row & 7)) << 4) + rem);
}

__global__ __launch_bounds__(256, 2) void k_fused(const float* __restrict__ bp3,
                                                  float* __restrict__ out) {
    extern __shared__ char sm[];
    const int n = blockIdx.y, sx = blockIdx.x;
    const int tid = threadIdx.x, lane = tid & 31, wid = tid >> 5;
    const int m0w = (wid >> 1) * 64, n0w = (wid & 1) * 32;
    const uint32_t smb = smem_u32(sm);

    const int a_r = lane & 15, a_kb = (lane >> 4) * 16;
    const int bt_r = (lane & 7) + 8 * ((lane >> 3) & 1);
    const int bt_s = lane >> 4;

    float acc[4][4][4];
#pragma unroll
    for (int i = 0; i < 4; i++)
#pragma unroll
        for (int j = 0; j < 4; j++)
#pragma unroll
            for (int p = 0; p < 4; p++) acc[i][j][p] = 0.f;

    auto issueA = [&](int g1, int buf) {
        const char* Ah = (g1 < 16) ? (const char*)&g_wph[0][0] : (const char*)&g_t7h[n][0][0];
        const char* Al = (g1 < 16) ? (const char*)&g_wpl[0][0] : (const char*)&g_t7l[n][0][0];
        const int kb = (g1 & 15) * 32;   // byte offset of 16 kcols
        const uint32_t pH = smb + 2 * FBX + (buf * 2 + 0) * FACH;
        const uint32_t pL = smb + 2 * FBX + (buf * 2 + 1) * FACH;
#pragma unroll
        for (int i = 0; i < 2; i++) {
            const int idx = tid + i * 256;
            const int r = idx >> 1, s = (idx & 1) * 16;
            cpa(pH + (uint32_t)r * FSTRIDE + s, Ah + (size_t)r * 512 + kb + s);
            cpa(pL + (uint32_t)r * FSTRIDE + s, Al + (size_t)r * 512 + kb + s);
        }
    };

    {   // B = x stripe [256 k-rows][64 cols] hi/lo, swizzled
        const char* srcH = (const char*)&g_xh[n][0][sx * 64];
        const char* srcL = (const char*)&g_xl[n][0][sx * 64];
#pragma unroll
        for (int i = 0; i < 8; i++) {
            const int idx = tid + i * 256;
            const int r = idx >> 3, s = idx & 7;
            const uint32_t off = bswz(r, s, 0);
            cpa(smb + off, srcH + (size_t)r * (HW * 2) + s * 16);
            cpa(smb + FBX + off, srcL + (size_t)r * (HW * 2) + s * 16);
        }
    }
    issueA(0, 0);
    CPA_COMMIT();

    for (int g = 0; g < 32; g++) {
        const int buf = g & 1;
        if (g < 31) { issueA(g + 1, buf ^ 1); CPA_COMMIT(); CPA_WAIT1(); }
        else CPA_WAIT0();
        __syncthreads();

        if (g == 16) {
            // stage0 epilogue: t6 = max(t3 + bias, sin(pi/2 x)); rewrite B
#pragma unroll
            for (int mt = 0; mt < 4; mt++)
#pragma unroll
                for (int h = 0; h < 2; h++) {
                    const int c = m0w + mt * 16 + (lane >> 2) + h * 8;
                    const float bias = __ldg(&bp3[c]);
#pragma unroll
                    for (int nt = 0; nt < 4; nt++) {
                        const int j = n0w + nt * 8 + (lane & 3) * 2;
                        const uint32_t off = bswz(c, j >> 3, (j * 2) & 15);
                        uint32_t ph = *(uint32_t*)(sm + off);
                        uint32_t pl = *(uint32_t*)(sm + FBX + off);
                        const float x0 = bflo(ph) + bflo(pl);
                        const float x1 = bfhi(ph) + bfhi(pl);
                        const float t60 = fmaxf(acc[mt][nt][h * 2] + bias,
                                                sinf(PI_HALF * x0));
                        const float t61 = fmaxf(acc[mt][nt][h * 2 + 1] + bias,
                                                sinf(PI_HALF * x1));
                        __nv_bfloat16 h0 = __float2bfloat16(t60);
                        __nv_bfloat16 h1 = __float2bfloat16(t61);
                        *(uint32_t*)(sm + off) = pk2(h0, h1);
                        *(uint32_t*)(sm + FBX + off) =
                            pk2(__float2bfloat16(t60 - __bfloat162float(h0)),
                                __float2bfloat16(t61 - __bfloat162float(h1)));
                        acc[mt][nt][h * 2] = 0.f;
                        acc[mt][nt][h * 2 + 1] = 0.f;
                    }
                }
            __syncthreads();
        }

        const uint32_t aHb = smb + 2 * FBX + (buf * 2 + 0) * FACH;
        const uint32_t aLb = smb + 2 * FBX + (buf * 2 + 1) * FACH;
        const int kg = (g & 15) * 16;
        uint32_t a[4][4], bh[4][2], bl[4][2];
#pragma unroll
        for (int mt = 0; mt < 4; mt++)
            ldsm4(a[mt], aHb + (uint32_t)(m0w + mt * 16 + a_r) * FSTRIDE + a_kb);
#pragma unroll
        for (int nt2 = 0; nt2 < 2; nt2++) {
            const int row = kg + bt_r;
            const int slot = ((n0w + nt2 * 16) >> 3) + bt_s;
            const uint32_t ro = bswz(row, slot, 0);
            uint32_t t[4];
            ldsm4t(t, smb + ro);
            bh[nt2 * 2][0] = t[0]; bh[nt2 * 2][1] = t[1];
            bh[nt2 * 2 + 1][0] = t[2]; bh[nt2 * 2 + 1][1] = t[3];
            ldsm4t(t, smb + FBX + ro);
            bl[nt2 * 2][0] = t[0]; bl[nt2 * 2][1] = t[1];
            bl[nt2 * 2 + 1][0] = t[2]; bl[nt2 * 2 + 1][1] = t[3];
        }
#pragma unroll
        for (int mt = 0; mt < 4; mt++)
#pragma unroll
            for (int nt = 0; nt < 4; nt++) {
                mma_bf16(acc[mt][nt], a[mt], bh[nt]);
                mma_bf16(acc[mt][nt], a[mt], bl[nt]);
            }
#pragma unroll
        for (int mt = 0; mt < 4; mt++)
            ldsm4(a[mt], aLb + (uint32_t)(m0w + mt * 16 + a_r) * FSTRIDE + a_kb);
#pragma unroll
        for (int mt = 0; mt < 4; mt++)
#pragma unroll
            for (int nt = 0; nt < 4; nt++)
                mma_bf16(acc[mt][nt], a[mt], bh[nt]);
        __syncthreads();
    }

    float* ob = out + (size_t)n * CC * HW + sx * 64;
#pragma unroll
    for (int mt = 0; mt < 4; mt++)
#pragma unroll
        for (int h = 0; h < 2; h++) {
            const int d = m0w + mt * 16 + (lane >> 2) + h * 8;
#pragma unroll
            for (int nt = 0; nt < 4; nt++) {
                const int j = n0w + nt * 8 + (lane & 3) * 2;
                *(float2*)(ob + (size_t)d * HW + j) =
                    make_float2(acc[mt][nt][h * 2], acc[mt][nt][h * 2 + 1]);
            }
        }
}

extern "C" void kernel_launch(void* const* d_in, const int* in_sizes, int n_in,
                              void* d_out, int out_size) {
    (void)in_sizes; (void)n_in; (void)out_size;
    const float* x   = (const float*)d_in[0];
    const float* Wp3 = (const float*)d_in[1];
    const float* bp3 = (const float*)d_in[2];
    const float* Wg1 = (const float*)d_in[3];
    const float* bg1 = (const float*)d_in[4];
    const float* Wg2 = (const float*)d_in[5];
    const float* bg2 = (const float*)d_in[6];
    const float* p7w = (const float*)d_in[7];
    float* out = (float*)d_out;

    cudaFuncSetAttribute(k_gram,  cudaFuncAttributeMaxDynamicSharedMemorySize, GRAM_SMEM);
    cudaFuncSetAttribute(k_fused, cudaFuncAttributeMaxDynamicSharedMemorySize, FUSED_SMEM);

    k_wprep<<<256, 256>>>(Wp3);
    k_prep<<<dim3(256, 32), 256>>>(x);
    k_uv<<<32, 256>>>(Wg1, Wg2);
    k_gram<<<dim3(3, 32, 3), 256, GRAM_SMEM>>>();
    k_t7<<<dim3(8, 8, 32), dim3(32, 32)>>>(Wg1, bg1, Wg2, bg2, p7w);
    k_fused<<<dim3(49, 32), 256, FUSED_SMEM>>>(bp3, out);
}

// round 7
// speedup vs baseline: 1.2676x; 1.0915x over previous
#include <cuda_runtime.h>
#include <cuda_bf16.h>
#include <stdint.h>
#include <math.h>

#define NB 32
#define CC 256
#define HW 3136
#define PI_HALF 1.57079632679489662f

__device__ __nv_bfloat16 g_xh[NB][CC][HW];
__device__ __nv_bfloat16 g_xl[NB][CC][HW];
__device__ float g_gramp[3][NB][CC][CC];
__device__ float g_rowsum[NB][CC];
__device__ float g_u[NB][CC];
__device__ float g_v[NB][CC];
__device__ __nv_bfloat16 g_wph[CC][CC];
__device__ __nv_bfloat16 g_wpl[CC][CC];
__device__ __nv_bfloat16 g_t7h[NB][CC][CC];   // t7^T [d][c], bf16 hi
__device__ __nv_bfloat16 g_t7l[NB][CC][CC];   // t7^T [d][c], bf16 lo

__device__ __forceinline__ uint32_t smem_u32(const void* p) {
    uint32_t a;
    asm("{ .reg .u64 t; cvta.to.shared.u64 t, %1; cvt.u32.u64 %0, t; }"
        : "=r"(a) : "l"(p));
    return a;
}
__device__ __forceinline__ void cpa(uint32_t s, const void* g) {
    asm volatile("cp.async.cg.shared.global [%0], [%1], 16;" :: "r"(s), "l"(g));
}
#define CPA_COMMIT() asm volatile("cp.async.commit_group;" ::: "memory")
#define CPA_WAIT0()  asm volatile("cp.async.wait_group 0;" ::: "memory")

__device__ __forceinline__ void ldsm4(uint32_t r[4], uint32_t a) {
    asm volatile("ldmatrix.sync.aligned.m8n8.x4.shared.b16 {%0,%1,%2,%3}, [%4];"
                 : "=r"(r[0]), "=r"(r[1]), "=r"(r[2]), "=r"(r[3]) : "r"(a));
}
__device__ __forceinline__ void ldsm4t(uint32_t r[4], uint32_t a) {
    asm volatile("ldmatrix.sync.aligned.m8n8.x4.trans.shared.b16 {%0,%1,%2,%3}, [%4];"
                 : "=r"(r[0]), "=r"(r[1]), "=r"(r[2]), "=r"(r[3]) : "r"(a));
}
__device__ __forceinline__ void mma_bf16(float c[4], const uint32_t a[4],
                                         const uint32_t b[2]) {
    asm volatile(
        "mma.sync.aligned.m16n8k16.row.col.f32.bf16.bf16.f32 "
        "{%0,%1,%2,%3}, {%4,%5,%6,%7}, {%8,%9}, {%0,%1,%2,%3};"
        : "+f"(c[0]), "+f"(c[1]), "+f"(c[2]), "+f"(c[3])
        : "r"(a[0]), "r"(a[1]), "r"(a[2]), "r"(a[3]), "r"(b[0]), "r"(b[1]));
}
__device__ __forceinline__ uint32_t pk2(__nv_bfloat16 a, __nv_bfloat16 b) {
    unsigned short ua = *(unsigned short*)&a, ub = *(unsigned short*)&b;
    return (uint32_t)ua | ((uint32_t)ub << 16);
}
__device__ __forceinline__ float bflo(uint32_t v) {
    unsigned short u = (unsigned short)(v & 0xffffu);
    return __bfloat162float(*(__nv_bfloat16*)&u);
}
__device__ __forceinline__ float bfhi(uint32_t v) {
    unsigned short u = (unsigned short)(v >> 16);
    return __bfloat162float(*(__nv_bfloat16*)&u);
}

// ---- prep: x -> bf16 hi/lo + rowsums ----------------------------------------
__global__ void k_prep(const float* __restrict__ x) {
    const int n = blockIdx.y, c = blockIdx.x, t = threadIdx.x;
    const float4* row = (const float4*)(x + ((size_t)n * CC + c) * HW);
    uint2* oh = (uint2*)&g_xh[n][c][0];
    uint2* ol = (uint2*)&g_xl[n][c][0];
    float s = 0.f;
    for (int u = t; u < HW / 4; u += 256) {
        float4 v = row[u];
        s += v.x + v.y + v.z + v.w;
        __nv_bfloat16 h0 = __float2bfloat16(v.x), h1 = __float2bfloat16(v.y);
        __nv_bfloat16 h2 = __float2bfloat16(v.z), h3 = __float2bfloat16(v.w);
        uint2 ph, pl;
        ph.x = pk2(h0, h1); ph.y = pk2(h2, h3);
        pl.x = pk2(__float2bfloat16(v.x - __bfloat162float(h0)),
                   __float2bfloat16(v.y - __bfloat162float(h1)));
        pl.y = pk2(__float2bfloat16(v.z - __bfloat162float(h2)),
                   __float2bfloat16(v.w - __bfloat162float(h3)));
        oh[u] = ph; ol[u] = pl;
    }
#pragma unroll
    for (int o = 16; o; o >>= 1) s += __shfl_down_sync(0xffffffffu, s, o);
    __shared__ float red[8];
    if ((t & 31) == 0) red[t >> 5] = s;
    __syncthreads();
    if (t == 0) {
        float tt = 0.f;
#pragma unroll
        for (int q = 0; q < 8; q++) tt += red[q];
        g_rowsum[n][c] = tt;
    }
}

__global__ void k_wprep(const float* __restrict__ w) {
    const int o = blockIdx.x, i = threadIdx.x;
    const float v = w[o * 256 + i];
    __nv_bfloat16 h = __float2bfloat16(v);
    g_wph[o][i] = h;
    g_wpl[o][i] = __float2bfloat16(v - __bfloat162float(h));
}

__global__ void k_uv(const float* __restrict__ Wg1, const float* __restrict__ Wg2) {
    const int n = blockIdx.x, t = threadIdx.x;
    __shared__ float ss[256];
    ss[t] = g_rowsum[n][t];
    __syncthreads();
    const int g = t >> 5, r = t & 31;
    float u = 0.f, v = 0.f;
#pragma unroll
    for (int i = 0; i < 32; i++) {
        u += Wg1[(g * 32 + r) * 32 + i] * ss[g * 32 + i];
        v += Wg2[(g * 32 + r) * 32 + i] * ss[g * 32 + i];
    }
    g_u[n][t] = u;
    g_v[n][t] = v;
}

// ---- Gram = x x^T, symmetric-tile, K-split x3, single-bar pipeline ----------
#define GSTRIDE 80u
#define GCH 10240
#define GRAM_SMEM (8 * GCH)

// grid (3, NB, 3): q=0 diag(0,0), q=1 diag(128,128), q=2 offdiag(0,128); z=ks
__global__ __launch_bounds__(256, 2) void k_gram() {
    extern __shared__ char sm[];
    const int q = blockIdx.x, n = blockIdx.y, ks = blockIdx.z;
    const int c0 = (q == 1) ? 128 : 0;
    const int d0 = (q == 0) ? 0 : 128;
    const bool diag = (q < 2);
    const int tid = threadIdx.x, lane = tid & 31, wid = tid >> 5;
    const int m0w = (wid & 1) * 64, n0w = (wid >> 1) * 32;
    const uint32_t smb = smem_u32(sm);

    const char* gAh = (const char*)&g_xh[n][c0][0];
    const char* gAl = (const char*)&g_xl[n][c0][0];
    const char* gBh = (const char*)&g_xh[n][d0][0];
    const char* gBl = (const char*)&g_xl[n][d0][0];

    const int lr = tid >> 1, ls = (tid & 1) * 32;
    const int a_r = lane & 15, a_kb = (lane >> 4) * 16;
    const int b_r = (lane & 7) + 8 * (lane >> 4);
    const int b_kb = ((lane >> 3) & 1) * 16;

    float acc[4][4][4];
#pragma unroll
    for (int i = 0; i < 4; i++)
#pragma unroll
        for (int j = 0; j < 4; j++)
#pragma unroll
            for (int p = 0; p < 4; p++) acc[i][j][p] = 0.f;

    const int ck0 = ks * 33;
    const int nck = (ks < 2) ? 33 : 32;
    const uint32_t so = (uint32_t)lr * GSTRIDE + ls;

    auto issueG = [&](int ci, int buf) {
        const size_t go = (size_t)lr * (HW * 2) + (size_t)(ck0 + ci) * 64 + ls;
        const uint32_t aH = smb + (buf * 2 + 0) * GCH + so;
        const uint32_t aL = smb + (buf * 2 + 1) * GCH + so;
        cpa(aH, gAh + go); cpa(aH + 16, gAh + go + 16);
        cpa(aL, gAl + go); cpa(aL + 16, gAl + go + 16);
        if (!diag) {
            const uint32_t bH = smb + 4 * GCH + (buf * 2 + 0) * GCH + so;
            const uint32_t bL = smb + 4 * GCH + (buf * 2 + 1) * GCH + so;
            cpa(bH, gBh + go); cpa(bH + 16, gBh + go + 16);
            cpa(bL, gBl + go); cpa(bL + 16, gBl + go + 16);
        }
    };

    issueG(0, 0);
    CPA_COMMIT();

    for (int ci = 0; ci < nck; ci++) {
        const int buf = ci & 1;
        CPA_WAIT0();
        __syncthreads();
        if (ci < nck - 1) { issueG(ci + 1, buf ^ 1); CPA_COMMIT(); }

        const uint32_t aHb = smb + (buf * 2 + 0) * GCH;
        const uint32_t aLb = smb + (buf * 2 + 1) * GCH;
        const uint32_t bHb = diag ? aHb : smb + 4 * GCH + (buf * 2 + 0) * GCH;
        const uint32_t bLb = diag ? aLb : smb + 4 * GCH + (buf * 2 + 1) * GCH;
#pragma unroll
        for (int kk = 0; kk < 2; kk++) {
            const uint32_t kbo = kk * 32;
            uint32_t a[4][4], bh[4][2], bl[4][2];
#pragma unroll
            for (int mt = 0; mt < 4; mt++)
                ldsm4(a[mt], aHb + (uint32_t)(m0w + mt * 16 + a_r) * GSTRIDE + a_kb + kbo);
#pragma unroll
            for (int nt2 = 0; nt2 < 2; nt2++) {
                const uint32_t ro = (uint32_t)(n0w + nt2 * 16 + b_r) * GSTRIDE + b_kb + kbo;
                uint32_t t[4];
                ldsm4(t, bHb + ro);
                bh[nt2 * 2][0] = t[0]; bh[nt2 * 2][1] = t[1];
                bh[nt2 * 2 + 1][0] = t[2]; bh[nt2 * 2 + 1][1] = t[3];
                ldsm4(t, bLb + ro);
                bl[nt2 * 2][0] = t[0]; bl[nt2 * 2][1] = t[1];
                bl[nt2 * 2 + 1][0] = t[2]; bl[nt2 * 2 + 1][1] = t[3];
            }
#pragma unroll
            for (int mt = 0; mt < 4; mt++)
#pragma unroll
                for (int nt = 0; nt < 4; nt++) {
                    mma_bf16(acc[mt][nt], a[mt], bh[nt]);
                    mma_bf16(acc[mt][nt], a[mt], bl[nt]);
                }
#pragma unroll
            for (int mt = 0; mt < 4; mt++)
                ldsm4(a[mt], aLb + (uint32_t)(m0w + mt * 16 + a_r) * GSTRIDE + a_kb + kbo);
#pragma unroll
            for (int mt = 0; mt < 4; mt++)
#pragma unroll
                for (int nt = 0; nt < 4; nt++)
                    mma_bf16(acc[mt][nt], a[mt], bh[nt]);
        }
        __syncthreads();
    }

    float* gout = &g_gramp[ks][n][0][0];
#pragma unroll
    for (int mt = 0; mt < 4; mt++)
#pragma unroll
        for (int h = 0; h < 2; h++) {
            const int c = c0 + m0w + mt * 16 + (lane >> 2) + h * 8;
#pragma unroll
            for (int nt = 0; nt < 4; nt++) {
                const int d = d0 + n0w + nt * 8 + (lane & 3) * 2;
                const float v0 = acc[mt][nt][h * 2], v1 = acc[mt][nt][h * 2 + 1];
                *(float2*)(gout + (size_t)c * CC + d) = make_float2(v0, v1);
                if (!diag) {
                    gout[(size_t)d * CC + c] = v0;
                    gout[(size_t)(d + 1) * CC + c] = v1;
                }
            }
        }
}

// ---- t7^T (split bf16, pre-scaled by 1/(56*16)) ------------------------------
__global__ void k_t7(const float* __restrict__ Wg1, const float* __restrict__ bg1,
                     const float* __restrict__ Wg2, const float* __restrict__ bg2,
                     const float* __restrict__ p7w) {
    __shared__ float W1s[32][33], W2s[32][33], Gs[32][33], Ms[32][33];
    const int n = blockIdx.z, g = blockIdx.y, h = blockIdx.x;
    const int tx = threadIdx.x, ty = threadIdx.y;

    W1s[ty][tx] = Wg1[(g * 32 + ty) * 32 + tx];
    W2s[ty][tx] = Wg2[(h * 32 + ty) * 32 + tx];
    Gs[ty][tx]  = g_gramp[0][n][g * 32 + ty][h * 32 + tx]
                + g_gramp[1][n][g * 32 + ty][h * 32 + tx]
                + g_gramp[2][n][g * 32 + ty][h * 32 + tx];
    __syncthreads();

    float m = 0.f;
#pragma unroll
    for (int i = 0; i < 32; i++) m += W1s[ty][i] * Gs[i][tx];
    Ms[ty][tx] = m;
    __syncthreads();

    float t5 = 0.f;
#pragma unroll
    for (int j = 0; j < 32; j++) t5 += Ms[ty][j] * W2s[tx][j];

    const int c = g * 32 + ty, d = h * 32 + tx;
    const float b1 = bg1[c], b2 = bg2[d];
    t5 += b1 * g_v[n][d] + g_u[n][c] * b2 + (float)HW * b1 * b2;
    const float val = p7w[c * 256 + d] * t5 * (1.0f / 896.0f);

    __syncthreads();
    W1s[ty][tx] = val;
    __syncthreads();
    const float tv = W1s[tx][ty];
    const int dd = h * 32 + ty, cc = g * 32 + tx;
    __nv_bfloat16 hh = __float2bfloat16(tv);
    g_t7h[n][dd][cc] = hh;
    g_t7l[n][dd][cc] = __float2bfloat16(tv - __bfloat162float(hh));
}

// ---- fused: 32 chunks k=16, swizzled B, single-bar pipeline, 2 CTAs/SM ------
#define FBX 32768
#define FSTRIDE 48u
#define FACH 12288
#define FUSED_SMEM (2 * FBX + 4 * FACH)   // 114688

__device__ __forceinline__ uint32_t bswz(int row, int slot, int rem) {
    return (uint32_t)(row * 128 + ((slot ^ (row & 7)) << 4) + rem);
}

__global__ __launch_bounds__(256, 2) void k_fused(const float* __restrict__ bp3,
                                                  float* __restrict__ out) {
    extern __shared__ char sm[];
    const int n = blockIdx.y, sx = blockIdx.x;
    const int tid = threadIdx.x, lane = tid & 31, wid = tid >> 5;
    const int m0w = (wid >> 1) * 64, n0w = (wid & 1) * 32;
    const uint32_t smb = smem_u32(sm);

    const int a_r = lane & 15, a_kb = (lane >> 4) * 16;
    const int bt_r = (lane & 7) + 8 * ((lane >> 3) & 1);
    const int bt_s = lane >> 4;

    float acc[4][4][4];
#pragma unroll
    for (int i = 0; i < 4; i++)
#pragma unroll
        for (int j = 0; j < 4; j++)
#pragma unroll
            for (int p = 0; p < 4; p++) acc[i][j][p] = 0.f;

    auto issueA = [&](int g1, int buf) {
        const char* Ah = (g1 < 16) ? (const char*)&g_wph[0][0] : (const char*)&g_t7h[n][0][0];
        const char* Al = (g1 < 16) ? (const char*)&g_wpl[0][0] : (const char*)&g_t7l[n][0][0];
        const int kb = (g1 & 15) * 32;   // byte offset of 16 kcols
        const uint32_t pH = smb + 2 * FBX + (buf * 2 + 0) * FACH;
        const uint32_t pL = smb + 2 * FBX + (buf * 2 + 1) * FACH;
#pragma unroll
        for (int i = 0; i < 2; i++) {
            const int idx = tid + i * 256;
            const int r = idx >> 1, s = (idx & 1) * 16;
            cpa(pH + (uint32_t)r * FSTRIDE + s, Ah + (size_t)r * 512 + kb + s);
            cpa(pL + (uint32_t)r * FSTRIDE + s, Al + (size_t)r * 512 + kb + s);
        }
    };

    {   // B = x stripe [256 k-rows][64 cols] hi/lo, swizzled
        const char* srcH = (const char*)&g_xh[n][0][sx * 64];
        const char* srcL = (const char*)&g_xl[n][0][sx * 64];
#pragma unroll
        for (int i = 0; i < 8; i++) {
            const int idx = tid + i * 256;
            const int r = idx >> 3, s = idx & 7;
            const uint32_t off = bswz(r, s, 0);
            cpa(smb + off, srcH + (size_t)r * (HW * 2) + s * 16);
            cpa(smb + FBX + off, srcL + (size_t)r * (HW * 2) + s * 16);
        }
    }
    issueA(0, 0);
    CPA_COMMIT();

    for (int g = 0; g < 32; g++) {
        const int buf = g & 1;
        CPA_WAIT0();
        __syncthreads();
        if (g < 31) { issueA(g + 1, buf ^ 1); CPA_COMMIT(); }

        if (g == 16) {
            // stage0 epilogue: t6 = max(t3 + bias, sin(pi/2 x)); rewrite B
#pragma unroll
            for (int mt = 0; mt < 4; mt++)
#pragma unroll
                for (int h = 0; h < 2; h++) {
                    const int c = m0w + mt * 16 + (lane >> 2) + h * 8;
                    const float bias = __ldg(&bp3[c]);
#pragma unroll
                    for (int nt = 0; nt < 4; nt++) {
                        const int j = n0w + nt * 8 + (lane & 3) * 2;
                        const uint32_t off = bswz(c, j >> 3, (j * 2) & 15);
                        uint32_t ph = *(uint32_t*)(sm + off);
                        uint32_t pl = *(uint32_t*)(sm + FBX + off);
                        const float x0 = bflo(ph) + bflo(pl);
                        const float x1 = bfhi(ph) + bfhi(pl);
                        const float t60 = fmaxf(acc[mt][nt][h * 2] + bias,
                                                __sinf(PI_HALF * x0));
                        const float t61 = fmaxf(acc[mt][nt][h * 2 + 1] + bias,
                                                __sinf(PI_HALF * x1));
                        __nv_bfloat16 h0 = __float2bfloat16(t60);
                        __nv_bfloat16 h1 = __float2bfloat16(t61);
                        *(uint32_t*)(sm + off) = pk2(h0, h1);
                        *(uint32_t*)(sm + FBX + off) =
                            pk2(__float2bfloat16(t60 - __bfloat162float(h0)),
                                __float2bfloat16(t61 - __bfloat162float(h1)));
                        acc[mt][nt][h * 2] = 0.f;
                        acc[mt][nt][h * 2 + 1] = 0.f;
                    }
                }
            __syncthreads();
        }

        const uint32_t aHb = smb + 2 * FBX + (buf * 2 + 0) * FACH;
        const uint32_t aLb = smb + 2 * FBX + (buf * 2 + 1) * FACH;
        const int kg = (g & 15) * 16;
        uint32_t a[4][4], bh[4][2], bl[4][2];
#pragma unroll
        for (int mt = 0; mt < 4; mt++)
            ldsm4(a[mt], aHb + (uint32_t)(m0w + mt * 16 + a_r) * FSTRIDE + a_kb);
#pragma unroll
        for (int nt2 = 0; nt2 < 2; nt2++) {
            const int row = kg + bt_r;
            const int slot = ((n0w + nt2 * 16) >> 3) + bt_s;
            const uint32_t ro = bswz(row, slot, 0);
            uint32_t t[4];
            ldsm4t(t, smb + ro);
            bh[nt2 * 2][0] = t[0]; bh[nt2 * 2][1] = t[1];
            bh[nt2 * 2 + 1][0] = t[2]; bh[nt2 * 2 + 1][1] = t[3];
            ldsm4t(t, smb + FBX + ro);
            bl[nt2 * 2][0] = t[0]; bl[nt2 * 2][1] = t[1];
            bl[nt2 * 2 + 1][0] = t[2]; bl[nt2 * 2 + 1][1] = t[3];
        }
#pragma unroll
        for (int mt = 0; mt < 4; mt++)
#pragma unroll
            for (int nt = 0; nt < 4; nt++) {
                mma_bf16(acc[mt][nt], a[mt], bh[nt]);
                mma_bf16(acc[mt][nt], a[mt], bl[nt]);
            }
#pragma unroll
        for (int mt = 0; mt < 4; mt++)
            ldsm4(a[mt], aLb + (uint32_t)(m0w + mt * 16 + a_r) * FSTRIDE + a_kb);
#pragma unroll
        for (int mt = 0; mt < 4; mt++)
#pragma unroll
            for (int nt = 0; nt < 4; nt++)
                mma_bf16(acc[mt][nt], a[mt], bh[nt]);
        __syncthreads();
    }

    float* ob = out + (size_t)n * CC * HW + sx * 64;
#pragma unroll
    for (int mt = 0; mt < 4; mt++)
#pragma unroll
        for (int h = 0; h < 2; h++) {
            const int d = m0w + mt * 16 + (lane >> 2) + h * 8;
#pragma unroll
            for (int nt = 0; nt < 4; nt++) {
                const int j = n0w + nt * 8 + (lane & 3) * 2;
                *(float2*)(ob + (size_t)d * HW + j) =
                    make_float2(acc[mt][nt][h * 2], acc[mt][nt][h * 2 + 1]);
            }
        }
}

extern "C" void kernel_launch(void* const* d_in, const int* in_sizes, int n_in,
                              void* d_out, int out_size) {
    (void)in_sizes; (void)n_in; (void)out_size;
    const float* x   = (const float*)d_in[0];
    const float* Wp3 = (const float*)d_in[1];
    const float* bp3 = (const float*)d_in[2];
    const float* Wg1 = (const float*)d_in[3];
    const float* bg1 = (const float*)d_in[4];
    const float* Wg2 = (const float*)d_in[5];
    const float* bg2 = (const float*)d_in[6];
    const float* p7w = (const float*)d_in[7];
    float* out = (float*)d_out;

    cudaFuncSetAttribute(k_gram,  cudaFuncAttributeMaxDynamicSharedMemorySize, GRAM_SMEM);
    cudaFuncSetAttribute(k_fused, cudaFuncAttributeMaxDynamicSharedMemorySize, FUSED_SMEM);

    k_wprep<<<256, 256>>>(Wp3);
    k_prep<<<dim3(256, 32), 256>>>(x);
    k_uv<<<32, 256>>>(Wg1, Wg2);
    k_gram<<<dim3(3, 32, 3), 256, GRAM_SMEM>>>();
    k_t7<<<dim3(8, 8, 32), dim3(32, 32)>>>(Wg1, bg1, Wg2, bg2, p7w);
    k_fused<<<dim3(49, 32), 256, FUSED_SMEM>>>(bp3, out);
}